// round 1
// baseline (speedup 1.0000x reference)
#include <cuda_runtime.h>

#define NN   8192
#define FIN  256
#define FOUT 128
#define ALPHA 0.2f
#define CJ   128          // j-chunk per iteration
#define TM   64           // rows per block (kernel 2)
#define PJ   132          // padded j-stride for p tile (multiple of 4 for float4)

__device__ float g_h[NN * FOUT];
__device__ float g_e1[NN];
__device__ float g_e2[NN];

union U64f2 { unsigned long long u; float2 f; };

__device__ __forceinline__ unsigned long long pk2(float a, float b) {
    U64f2 z; z.f = make_float2(a, b); return z.u;
}
#define FMA2(acc, a, b) asm("fma.rn.f32x2 %0, %1, %2, %0;" : "+l"(acc) : "l"(a), "l"(b))

// ---------------------------------------------------------------------------
// Kernel 1: h = x @ trans   (8192x256 @ 256x128, fp32)
// Block: 64 rows x 128 cols, TK=32, 256 threads, 8x4 micro-tile.
// ---------------------------------------------------------------------------
__global__ __launch_bounds__(256) void k_gemm_h(const float* __restrict__ x,
                                                const float* __restrict__ trans)
{
    __shared__ float xs[64 * 32];
    __shared__ float ts[32 * FOUT];
    const int t = threadIdx.x;
    const int rowbase = blockIdx.x * 64;
    const int ty = t >> 5;   // 8 row-groups of 8 rows
    const int tx = t & 31;   // 32 col-groups of 4 cols

    float acc[8][4];
    #pragma unroll
    for (int i = 0; i < 8; i++)
        #pragma unroll
        for (int c = 0; c < 4; c++) acc[i][c] = 0.f;

    const float4* x4 = (const float4*)x;
    const float4* t4 = (const float4*)trans;

    for (int k0 = 0; k0 < FIN; k0 += 32) {
        #pragma unroll
        for (int v = t, i = 0; i < 2; i++, v += 256) {   // 512 float4
            int r = v >> 3, c = v & 7;
            ((float4*)xs)[r * 8 + c] = x4[(size_t)(rowbase + r) * (FIN/4) + (k0 >> 2) + c];
        }
        #pragma unroll
        for (int v = t, i = 0; i < 4; i++, v += 256) {   // 1024 float4
            int r = v >> 5, c = v & 31;
            ((float4*)ts)[r * 32 + c] = t4[(size_t)(k0 + r) * (FOUT/4) + c];
        }
        __syncthreads();
        #pragma unroll
        for (int kk = 0; kk < 32; kk++) {
            float4 b = *(const float4*)&ts[kk * FOUT + tx * 4];
            #pragma unroll
            for (int i = 0; i < 8; i++) {
                float a = xs[(ty * 8 + i) * 32 + kk];
                acc[i][0] += a * b.x; acc[i][1] += a * b.y;
                acc[i][2] += a * b.z; acc[i][3] += a * b.w;
            }
        }
        __syncthreads();
    }
    #pragma unroll
    for (int i = 0; i < 8; i++) {
        float4 o = make_float4(acc[i][0], acc[i][1], acc[i][2], acc[i][3]);
        *(float4*)&g_h[(size_t)(rowbase + ty * 8 + i) * FOUT + tx * 4] = o;
    }
}

// ---------------------------------------------------------------------------
// Kernel 2: e1 = h @ a[:128], e2 = h @ a[128:]  (one warp per row)
// ---------------------------------------------------------------------------
__global__ __launch_bounds__(256) void k_e(const float* __restrict__ aw)
{
    const int row  = blockIdx.x * 8 + (threadIdx.x >> 5);
    const int lane = threadIdx.x & 31;
    float s1 = 0.f, s2 = 0.f;
    #pragma unroll
    for (int d = lane; d < FOUT; d += 32) {
        float v = g_h[(size_t)row * FOUT + d];
        s1 += v * aw[d];
        s2 += v * aw[FOUT + d];
    }
    #pragma unroll
    for (int o = 16; o; o >>= 1) {
        s1 += __shfl_xor_sync(0xFFFFFFFFu, s1, o);
        s2 += __shfl_xor_sync(0xFFFFFFFFu, s2, o);
    }
    if (lane == 0) { g_e1[row] = s1; g_e2[row] = s2; }
}

// ---------------------------------------------------------------------------
// Kernel 3: fused masked-softmax-attention + aggregation + ELU.
// Block = 64 rows x full 128 dims. 256 threads: jp = t>>7 splits the j-chunk
// into two halves; each half's 128 threads form an 8(row-group) x 16(d-group)
// grid with an 8x8 micro-tile accumulated in fma.rn.f32x2 pairs.
// Per chunk (CJ=128 j): build p~[64][128] in smem from adj/e1/e2, stage
// h[128][128] in smem, accumulate out += p~ * h and srow += p~.
// ---------------------------------------------------------------------------
__global__ __launch_bounds__(256) void k_main(const int* __restrict__ adj,
                                              float* __restrict__ out)
{
    extern __shared__ float sm[];
    float* p_s  = sm;                    // TM * PJ        (8448 f)
    float* hs   = sm + TM * PJ;          // CJ * FOUT      (16384 f)
    float* e1s  = hs + CJ * FOUT;        // TM
    float* e2s  = e1s + TM;              // CJ
    float* srow = e2s + CJ;              // TM

    const int t = threadIdx.x;
    const int rowbase = blockIdx.x * TM;
    const int jp = t >> 7;
    const int u  = t & 127;
    const int r0 = (u >> 4) * 8;         // 8 rows
    const int d0 = (u & 15) * 8;         // 8 dims

    if (t < TM) e1s[t] = g_e1[rowbase + t];

    unsigned long long acc[8][4];
    #pragma unroll
    for (int r = 0; r < 8; r++)
        #pragma unroll
        for (int c = 0; c < 4; c++) acc[r][c] = 0ull;

    float srow_reg = 0.f;
    const int4*   adj4 = (const int4*)adj;
    const float4* gh4  = (const float4*)g_h;

    for (int jc = 0; jc < NN; jc += CJ) {
        __syncthreads();   // previous chunk's smem readers done

        // prefetch adj tile: 64 rows x 128 ints = 2048 int4, 8 per thread
        int4 av[8];
        #pragma unroll
        for (int l = 0; l < 8; l++) {
            int v = l * 256 + t;
            int row = v >> 5, c4 = v & 31;
            av[l] = adj4[(size_t)(rowbase + row) * (NN/4) + (jc >> 2) + c4];
        }
        if (t < CJ) e2s[t] = g_e2[jc + t];
        // stage h chunk: 128 rows x 128 dims = 4096 float4
        #pragma unroll
        for (int i = 0; i < 16; i++) {
            int v = i * 256 + t;
            ((float4*)hs)[v] = gh4[(size_t)jc * (FOUT/4) + v];
        }
        __syncthreads();   // e2s/e1s ready; p_s free

        // p~ = adj ? exp(leakyrelu(e1_i + e2_j)) : 0
        #pragma unroll
        for (int l = 0; l < 8; l++) {
            int v = l * 256 + t;
            int row = v >> 5, c4 = v & 31;
            float e1v = e1s[row];
            int jl = c4 * 4;
            float4 pv; float s;
            s = e1v + e2s[jl + 0]; s = fmaxf(s, ALPHA * s); pv.x = av[l].x ? __expf(s) : 0.f;
            s = e1v + e2s[jl + 1]; s = fmaxf(s, ALPHA * s); pv.y = av[l].y ? __expf(s) : 0.f;
            s = e1v + e2s[jl + 2]; s = fmaxf(s, ALPHA * s); pv.z = av[l].z ? __expf(s) : 0.f;
            s = e1v + e2s[jl + 3]; s = fmaxf(s, ALPHA * s); pv.w = av[l].w ? __expf(s) : 0.f;
            *(float4*)&p_s[row * PJ + jl] = pv;
        }
        __syncthreads();   // p tile + h tile ready

        // per-row softmax denominator (thread t owns row t)
        if (t < TM) {
            float4 s4 = make_float4(0.f, 0.f, 0.f, 0.f);
            #pragma unroll
            for (int c = 0; c < CJ / 4; c++) {
                float4 v = *(const float4*)&p_s[t * PJ + c * 4];
                s4.x += v.x; s4.y += v.y; s4.z += v.z; s4.w += v.w;
            }
            srow_reg += (s4.x + s4.y) + (s4.z + s4.w);
        }

        // mainloop: acc[r][d-pair] += p~[r][j] * h[j][d-pair]
        const int jbase = jp * (CJ / 2);
        for (int j4 = 0; j4 < CJ / 2; j4 += 4) {
            float4 pv[8];
            #pragma unroll
            for (int r = 0; r < 8; r++)
                pv[r] = *(const float4*)&p_s[(r0 + r) * PJ + jbase + j4];
            #pragma unroll
            for (int q = 0; q < 4; q++) {
                const float* hrow = &hs[(jbase + j4 + q) * FOUT + d0];
                float4 ha = *(const float4*)hrow;
                float4 hb = *(const float4*)(hrow + 4);
                unsigned long long h0 = pk2(ha.x, ha.y);
                unsigned long long h1 = pk2(ha.z, ha.w);
                unsigned long long h2 = pk2(hb.x, hb.y);
                unsigned long long h3 = pk2(hb.z, hb.w);
                #pragma unroll
                for (int r = 0; r < 8; r++) {
                    float pq = (q == 0) ? pv[r].x : (q == 1) ? pv[r].y
                             : (q == 2) ? pv[r].z : pv[r].w;
                    unsigned long long pu = pk2(pq, pq);
                    FMA2(acc[r][0], pu, h0);
                    FMA2(acc[r][1], pu, h1);
                    FMA2(acc[r][2], pu, h2);
                    FMA2(acc[r][3], pu, h3);
                }
            }
        }
    }

    __syncthreads();
    if (t < TM) srow[t] = srow_reg;
    float* red = hs;   // reuse h staging as reduction buffer (64*128 <= 128*128)
    if (jp == 1) {
        #pragma unroll
        for (int r = 0; r < 8; r++)
            #pragma unroll
            for (int c = 0; c < 4; c++) {
                U64f2 z; z.u = acc[r][c];
                *(float2*)&red[(r0 + r) * FOUT + d0 + c * 2] = z.f;
            }
    }
    __syncthreads();
    if (jp == 0) {
        #pragma unroll
        for (int r = 0; r < 8; r++) {
            float inv = 1.f / srow[r0 + r];
            float o[8];
            #pragma unroll
            for (int c = 0; c < 4; c++) {
                U64f2 z; z.u = acc[r][c];
                float2 rv = *(const float2*)&red[(r0 + r) * FOUT + d0 + c * 2];
                float v0 = (z.f.x + rv.x) * inv;
                float v1 = (z.f.y + rv.y) * inv;
                o[c * 2]     = v0 > 0.f ? v0 : expm1f(v0);
                o[c * 2 + 1] = v1 > 0.f ? v1 : expm1f(v1);
            }
            float4* op = (float4*)&out[(size_t)(rowbase + r0 + r) * FOUT + d0];
            op[0] = make_float4(o[0], o[1], o[2], o[3]);
            op[1] = make_float4(o[4], o[5], o[6], o[7]);
        }
    }
}

// ---------------------------------------------------------------------------
extern "C" void kernel_launch(void* const* d_in, const int* in_sizes, int n_in,
                              void* d_out, int out_size)
{
    const float* x     = (const float*)d_in[0];
    const int*   adj   = (const int*)d_in[1];
    const float* trans = (const float*)d_in[2];
    const float* aw    = (const float*)d_in[3];
    float*       out   = (float*)d_out;

    const int smem_bytes = (TM * PJ + CJ * FOUT + TM + CJ + TM) * (int)sizeof(float);
    cudaFuncSetAttribute(k_main, cudaFuncAttributeMaxDynamicSharedMemorySize, smem_bytes);

    k_gemm_h<<<NN / 64, 256>>>(x, trans);
    k_e<<<NN / 8, 256>>>(aw);
    k_main<<<NN / TM, 256, smem_bytes>>>(adj, out);
}

// round 3
// speedup vs baseline: 2.4187x; 2.4187x over previous
#include <cuda_runtime.h>
#include <cuda_bf16.h>
#include <cstdint>

#define NN   8192
#define FIN  256
#define FOUT 128
#define L2E  1.44269504f
#define LRA  0.2f
#define CK   64                    // j per chunk
#define JSPLIT 4
#define JBLK (NN / JSPLIT)         // 2048
#define NCH  (JBLK / CK)           // 32 chunks per block
#define RBLK 256                   // rows per block
#define NTI  (NN / CK)             // 128 prebuilt B tiles
#define TERM_BYTES 16384           // one term (hi or lo): 64j x 128d x 2B
#define TILE_BYTES 32768           // hi + lo

__device__ __align__(16)  float g_h[NN * FOUT];
__device__ float g_e1s[NN];        // 1.4427 * e1
__device__ float g_e2s[NN];        // 1.4427 * e2
__device__ __align__(128) unsigned char g_bt[(size_t)NTI * TILE_BYTES];  // 4MB
__device__ __align__(16)  float g_part[JSPLIT][NN * FOUT];               // 16MB
__device__ float g_psum[JSPLIT][NN];

// ------------------------- helpers -----------------------------------------
__device__ __forceinline__ uint32_t smem_u32(const void* p) {
    uint32_t a;
    asm("{ .reg .u64 t; cvta.to.shared.u64 t, %1; cvt.u32.u64 %0, t; }" : "=r"(a) : "l"(p));
    return a;
}
__device__ __forceinline__ uint32_t packbf(float lo, float hi) {
    uint32_t r;  // low 16 bits = lo (element with lower k index)
    asm("cvt.rn.bf16x2.f32 %0, %1, %2;" : "=r"(r) : "f"(hi), "f"(lo));
    return r;
}
__device__ __forceinline__ void split2(float a, float b, uint32_t& hi, uint32_t& lo) {
    hi = packbf(a, b);
    float ra = a - __uint_as_float(hi << 16);
    float rb = b - __uint_as_float(hi & 0xFFFF0000u);
    lo = packbf(ra, rb);
}
__device__ __forceinline__ float pcalc(float se1, float se2, int a) {
    float s = se1 + se2;
    s = fmaxf(s, LRA * s);          // leakyrelu commutes with positive scaling
    float p;
    asm("ex2.approx.f32 %0, %1;" : "=f"(p) : "f"(s));
    return a ? p : 0.f;
}
__device__ __forceinline__ void mma16816(float* c, const uint32_t* a, const uint32_t* b) {
    asm volatile("mma.sync.aligned.m16n8k16.row.col.f32.bf16.bf16.f32 "
        "{%0,%1,%2,%3}, {%4,%5,%6,%7}, {%8,%9}, {%0,%1,%2,%3};"
        : "+f"(c[0]), "+f"(c[1]), "+f"(c[2]), "+f"(c[3])
        : "r"(a[0]), "r"(a[1]), "r"(a[2]), "r"(a[3]), "r"(b[0]), "r"(b[1]));
}
#define LDMX4(r, a) \
    asm volatile("ldmatrix.sync.aligned.m8n8.x4.shared.b16 {%0,%1,%2,%3}, [%4];" \
        : "=r"((r)[0]), "=r"((r)[1]), "=r"((r)[2]), "=r"((r)[3]) : "r"(a))
#define CP_ASYNC(dst, src) \
    asm volatile("cp.async.cg.shared.global [%0], [%1], 16;" :: "r"(dst), "l"(src))
#define CP_COMMIT() asm volatile("cp.async.commit_group;" ::: "memory")
#define CP_WAIT1()  asm volatile("cp.async.wait_group 1;"  ::: "memory")

// ---------------------------------------------------------------------------
// Kernel 1: h = x @ trans  (proven round-1 version)
// ---------------------------------------------------------------------------
__global__ __launch_bounds__(256) void k_gemm_h(const float* __restrict__ x,
                                                const float* __restrict__ trans)
{
    __shared__ float xs[64 * 32];
    __shared__ float ts[32 * FOUT];
    const int t = threadIdx.x;
    const int rowbase = blockIdx.x * 64;
    const int ty = t >> 5;
    const int tx = t & 31;

    float acc[8][4];
    #pragma unroll
    for (int i = 0; i < 8; i++)
        #pragma unroll
        for (int c = 0; c < 4; c++) acc[i][c] = 0.f;

    const float4* x4 = (const float4*)x;
    const float4* t4 = (const float4*)trans;

    for (int k0 = 0; k0 < FIN; k0 += 32) {
        #pragma unroll
        for (int v = t, i = 0; i < 2; i++, v += 256) {
            int r = v >> 3, c = v & 7;
            ((float4*)xs)[r * 8 + c] = x4[(size_t)(rowbase + r) * (FIN/4) + (k0 >> 2) + c];
        }
        #pragma unroll
        for (int v = t, i = 0; i < 4; i++, v += 256) {
            int r = v >> 5, c = v & 31;
            ((float4*)ts)[r * 32 + c] = t4[(size_t)(k0 + r) * (FOUT/4) + c];
        }
        __syncthreads();
        #pragma unroll
        for (int kk = 0; kk < 32; kk++) {
            float4 b = *(const float4*)&ts[kk * FOUT + tx * 4];
            #pragma unroll
            for (int i = 0; i < 8; i++) {
                float a = xs[(ty * 8 + i) * 32 + kk];
                acc[i][0] += a * b.x; acc[i][1] += a * b.y;
                acc[i][2] += a * b.z; acc[i][3] += a * b.w;
            }
        }
        __syncthreads();
    }
    #pragma unroll
    for (int i = 0; i < 8; i++) {
        float4 o = make_float4(acc[i][0], acc[i][1], acc[i][2], acc[i][3]);
        *(float4*)&g_h[(size_t)(rowbase + ty * 8 + i) * FOUT + tx * 4] = o;
    }
}

// ---------------------------------------------------------------------------
// Kernel 2: e1/e2 (pre-scaled by log2(e))
// ---------------------------------------------------------------------------
__global__ __launch_bounds__(256) void k_e(const float* __restrict__ aw)
{
    const int row  = blockIdx.x * 8 + (threadIdx.x >> 5);
    const int lane = threadIdx.x & 31;
    float s1 = 0.f, s2 = 0.f;
    #pragma unroll
    for (int d = lane; d < FOUT; d += 32) {
        float v = g_h[(size_t)row * FOUT + d];
        s1 += v * aw[d];
        s2 += v * aw[FOUT + d];
    }
    #pragma unroll
    for (int o = 16; o; o >>= 1) {
        s1 += __shfl_xor_sync(0xFFFFFFFFu, s1, o);
        s2 += __shfl_xor_sync(0xFFFFFFFFu, s2, o);
    }
    if (lane == 0) { g_e1s[row] = s1 * L2E; g_e2s[row] = s2 * L2E; }
}

// ---------------------------------------------------------------------------
// Kernel 3 (prep): build B = h^T tiles as ldmatrix-ready 8x8 b16 blocks.
// Block layout inside a tile (per term): blk = ((step*8+dpair)*2+dn)*2+kk,
// each blk = 128B: 8 rows (dr: d index) x 16B (8 j as bf16 pairs).
// Element (dr, jc) = h[j0 + step*16 + kk*8 + jc][dpair*16 + dn*8 + dr].
// ---------------------------------------------------------------------------
__global__ __launch_bounds__(256) void k_prep()
{
    const int tc = blockIdx.x;
    const int t  = threadIdx.x;
    const int j0 = tc * CK;
    unsigned char* tb = g_bt + (size_t)tc * TILE_BYTES;

    #pragma unroll
    for (int i = 0; i < 4; i++) {
        int rho = i * 256 + t;
        int blk = rho >> 3, dr = rho & 7;
        int kk = blk & 1, dn = (blk >> 1) & 1, dp = (blk >> 2) & 7, st = blk >> 5;
        int d  = dp * 16 + dn * 8 + dr;
        int jb = j0 + st * 16 + kk * 8;
        uint32_t hi4[4], lo4[4];
        #pragma unroll
        for (int m = 0; m < 4; m++) {
            float a = g_h[(size_t)(jb + 2*m)     * FOUT + d];
            float b = g_h[(size_t)(jb + 2*m + 1) * FOUT + d];
            split2(a, b, hi4[m], lo4[m]);
        }
        uint32_t off = (uint32_t)blk * 128 + dr * 16;
        *(uint4*)(tb + off)              = make_uint4(hi4[0], hi4[1], hi4[2], hi4[3]);
        *(uint4*)(tb + TERM_BYTES + off) = make_uint4(lo4[0], lo4[1], lo4[2], lo4[3]);
    }
}

// ---------------------------------------------------------------------------
// Kernel 4 (main): fused masked-exp + HMMA bf16-split attention GEMM.
// 8 warps, each m32 x n128; A fragments computed in-register; B via
// cp.async double-buffered smem + ldmatrix.x4; 3 precision terms.
// ---------------------------------------------------------------------------
__global__ __launch_bounds__(256, 1) void k_main(const int* __restrict__ adj)
{
    extern __shared__ unsigned char smem[];
    const uint32_t sb = smem_u32(smem);
    const int t = threadIdx.x, w = t >> 5, l = t & 31;
    const int bx = blockIdx.x, by = blockIdx.y;
    const int g = l >> 2, q2 = (l & 3) * 2;
    const int rowb = bx * RBLK + w * 32;
    const size_t jbase = (size_t)by * JBLK;

    // prime B double-buffer
    const unsigned char* bt0 = g_bt + (size_t)(by * NCH) * TILE_BYTES;
    #pragma unroll
    for (int c = 0; c < 2; c++) {
        uint32_t dst = sb + c * TILE_BYTES + t * 16;
        const unsigned char* src = bt0 + (size_t)c * TILE_BYTES + t * 16;
        #pragma unroll
        for (int i = 0; i < 8; i++) CP_ASYNC(dst + i * 4096, src + i * 4096);
        CP_COMMIT();
    }

    float se1[4];
    const int* rp[4];
    #pragma unroll
    for (int i = 0; i < 4; i++) {
        se1[i] = g_e1s[rowb + g + i * 8];
        rp[i]  = adj + (size_t)(rowb + g + i * 8) * NN;
    }

    float c_[2][16][4];
    #pragma unroll
    for (int mg = 0; mg < 2; mg++)
        #pragma unroll
        for (int td = 0; td < 16; td++)
            #pragma unroll
            for (int k = 0; k < 4; k++) c_[mg][td][k] = 0.f;
    float rs[4] = {0.f, 0.f, 0.f, 0.f};

    // adj prefetch for (c=0, s=0); j offsets advance by 16 per step
    size_t joff = jbase + q2;
    int2 aA[4], aB[4];
    #pragma unroll
    for (int i = 0; i < 4; i++) {
        aA[i] = __ldg((const int2*)(rp[i] + joff));
        aB[i] = __ldg((const int2*)(rp[i] + joff + 8));
    }

    for (int c = 0; c < NCH; c++) {
        CP_WAIT1();
        __syncthreads();
        const uint32_t bufb = sb + (c & 1) * TILE_BYTES;

        #pragma unroll
        for (int s = 0; s < 4; s++) {
            const float2 e2a = *(const float2*)(g_e2s + joff);
            const float2 e2b = *(const float2*)(g_e2s + joff + 8);

            uint32_t ahi[2][4], alo[2][4];
            #pragma unroll
            for (int i = 0; i < 4; i++) {
                float p0 = pcalc(se1[i], e2a.x, aA[i].x);
                float p1 = pcalc(se1[i], e2a.y, aA[i].y);
                float p2 = pcalc(se1[i], e2b.x, aB[i].x);
                float p3 = pcalc(se1[i], e2b.y, aB[i].y);
                rs[i] += (p0 + p1) + (p2 + p3);
                const int mg = i >> 1, hh = i & 1;
                split2(p0, p1, ahi[mg][hh],     alo[mg][hh]);
                split2(p2, p3, ahi[mg][2 + hh], alo[mg][2 + hh]);
            }

            // prefetch next step's adj (skip only at the very end)
            if (!(c == NCH - 1 && s == 3)) {
                joff += 16;
                #pragma unroll
                for (int i = 0; i < 4; i++) {
                    aA[i] = __ldg((const int2*)(rp[i] + joff));
                    aB[i] = __ldg((const int2*)(rp[i] + joff + 8));
                }
            }

            #pragma unroll
            for (int dp = 0; dp < 8; dp++) {
                uint32_t bh[4], bl[4];
                const uint32_t ad = bufb + (s * 8 + dp) * 512 + (l >> 3) * 128 + (l & 7) * 16;
                LDMX4(bh, ad);
                LDMX4(bl, ad + TERM_BYTES);
                #pragma unroll
                for (int mg = 0; mg < 2; mg++) {
                    float* c0 = c_[mg][2 * dp];
                    float* c1 = c_[mg][2 * dp + 1];
                    mma16816(c0, ahi[mg], bh);
                    mma16816(c1, ahi[mg], bh + 2);
                    mma16816(c0, alo[mg], bh);
                    mma16816(c1, alo[mg], bh + 2);
                    mma16816(c0, ahi[mg], bl);
                    mma16816(c1, ahi[mg], bl + 2);
                }
            }
        }

        __syncthreads();
        if (c + 2 < NCH) {
            uint32_t dst = sb + (c & 1) * TILE_BYTES + t * 16;
            const unsigned char* src = bt0 + (size_t)(c + 2) * TILE_BYTES + t * 16;
            #pragma unroll
            for (int i = 0; i < 8; i++) CP_ASYNC(dst + i * 4096, src + i * 4096);
        }
        CP_COMMIT();
    }

    // row sums: reduce over the 4 lanes sharing g
    #pragma unroll
    for (int i = 0; i < 4; i++) {
        rs[i] += __shfl_xor_sync(0xFFFFFFFFu, rs[i], 1);
        rs[i] += __shfl_xor_sync(0xFFFFFFFFu, rs[i], 2);
    }
    if ((l & 3) == 0) {
        #pragma unroll
        for (int i = 0; i < 4; i++)
            g_psum[by][rowb + g + i * 8] = rs[i];
    }

    // store unnormalized partials
    float* pb = g_part[by];
    #pragma unroll
    for (int mg = 0; mg < 2; mg++) {
        const int row0 = rowb + mg * 16 + g;
        #pragma unroll
        for (int td = 0; td < 16; td++) {
            const int col = td * 8 + q2;
            *(float2*)(pb + (size_t)row0 * FOUT + col) =
                make_float2(c_[mg][td][0], c_[mg][td][1]);
            *(float2*)(pb + (size_t)(row0 + 8) * FOUT + col) =
                make_float2(c_[mg][td][2], c_[mg][td][3]);
        }
    }
}

// ---------------------------------------------------------------------------
// Kernel 5 (final): combine j-split partials, normalize, ELU.
// ---------------------------------------------------------------------------
__global__ __launch_bounds__(256) void k_final(float* __restrict__ out)
{
    const int idx = blockIdx.x * 256 + threadIdx.x;   // float4 index
    const int r = idx >> 5;
    float4 v = make_float4(0.f, 0.f, 0.f, 0.f);
    #pragma unroll
    for (int p = 0; p < JSPLIT; p++) {
        float4 a = ((const float4*)g_part[p])[idx];
        v.x += a.x; v.y += a.y; v.z += a.z; v.w += a.w;
    }
    const float inv = 1.f / (g_psum[0][r] + g_psum[1][r] + g_psum[2][r] + g_psum[3][r]);
    float o[4] = { v.x * inv, v.y * inv, v.z * inv, v.w * inv };
    #pragma unroll
    for (int i = 0; i < 4; i++) o[i] = o[i] > 0.f ? o[i] : expm1f(o[i]);
    ((float4*)out)[idx] = make_float4(o[0], o[1], o[2], o[3]);
}

// ---------------------------------------------------------------------------
extern "C" void kernel_launch(void* const* d_in, const int* in_sizes, int n_in,
                              void* d_out, int out_size)
{
    const float* x     = (const float*)d_in[0];
    const int*   adj   = (const int*)d_in[1];
    const float* trans = (const float*)d_in[2];
    const float* aw    = (const float*)d_in[3];
    float*       out   = (float*)d_out;

    const int smem_bytes = 2 * TILE_BYTES;   // 64KB
    cudaFuncSetAttribute(k_main, cudaFuncAttributeMaxDynamicSharedMemorySize, smem_bytes);

    k_gemm_h<<<NN / 64, 256>>>(x, trans);
    k_e<<<NN / 8, 256>>>(aw);
    k_prep<<<NTI, 256>>>();
    dim3 gmain(NN / RBLK, JSPLIT);
    k_main<<<gmain, 256, smem_bytes>>>(adj);
    k_final<<<NN * FOUT / (256 * 4), 256>>>(out);
}